// round 3
// baseline (speedup 1.0000x reference)
#include <cuda_runtime.h>
#include <math.h>

// ---------------------------------------------------------------------------
// Model constants
// ---------------------------------------------------------------------------
#define BATCH   2
#define SEQ     1024
#define NROWS   (BATCH * SEQ)      // 2048
#define DMODEL  1024
#define NHEAD   16
#define HDIM    64
#define TDIM    1024               // NHEAD * HDIM
#define FFDIM   4096
#define NLAYER  8
#define VOCAB   32000

// ---------------------------------------------------------------------------
// Device scratch (allocation-free)
// ---------------------------------------------------------------------------
__device__ float g_x   [NROWS * DMODEL];   // residual stream
__device__ float g_xn  [NROWS * DMODEL];   // layernormed
__device__ float g_u   [NROWS * 3 * TDIM]; // qkv
__device__ float g_attn[NROWS * TDIM];     // attention out (pre-Wo)
__device__ float g_h   [NROWS * FFDIM];    // ffn hidden

// ---------------------------------------------------------------------------
// Helpers
// ---------------------------------------------------------------------------
__device__ __forceinline__ float gelu_exact(float v) {
    return 0.5f * v * (1.0f + erff(v * 0.70710678118654752440f));
}

__device__ __forceinline__ unsigned f2tf32(float f) {
    unsigned u;
    asm("cvt.rna.tf32.f32 %0, %1;" : "=r"(u) : "f"(f));
    return u;
}

__device__ __forceinline__ void mma_tf32(float* c, const unsigned* a, const unsigned* b) {
    asm volatile(
        "mma.sync.aligned.m16n8k8.row.col.f32.tf32.tf32.f32 "
        "{%0,%1,%2,%3},{%4,%5,%6,%7},{%8,%9},{%0,%1,%2,%3};"
        : "+f"(c[0]), "+f"(c[1]), "+f"(c[2]), "+f"(c[3])
        : "r"(a[0]), "r"(a[1]), "r"(a[2]), "r"(a[3]), "r"(b[0]), "r"(b[1]));
}

// ---------------------------------------------------------------------------
// Tensor-core GEMM (tf32): C[M,N] = A[M,K] @ B[N,K]^T  (+ epilogue)
// MODE 0: plain    MODE 1: gelu(acc + bias)    MODE 2: resid + acc (+ bias)
// M%128==0, N%128==0, K%16==0.
// Block 256 thr = 8 warps; tile 128x128, BK=16, double-buffered smem.
// smem layout [k][m|n] padded to 136 -> fragment LDS bank = (8t+g)%32, CF.
// ---------------------------------------------------------------------------
template<int MODE>
__global__ __launch_bounds__(256)
void gemm_mma(const float* __restrict__ A, const float* __restrict__ B,
              const float* __restrict__ bias, const float* __restrict__ resid,
              float* __restrict__ C, int M, int N, int K)
{
    constexpr int BK = 16;
    constexpr int LD = 136;
    __shared__ unsigned As[2][BK][LD];
    __shared__ unsigned Bs[2][BK][LD];

    const int bm = blockIdx.y * 128;
    const int bn = blockIdx.x * 128;
    const int tid  = threadIdx.x;
    const int warp = tid >> 5;
    const int lane = tid & 31;
    const int g = lane >> 2;       // group id 0..7
    const int t = lane & 3;        // thread-in-group 0..3
    const int moff = (warp & 3) * 32;
    const int noff = (warp >> 2) * 64;

    // global loader coords: 128 rows x 16 cols, 256 threads x 2 float4
    const int ldRow = tid >> 2;            // 0..63 (+64 for j=1)
    const int ldCol = (tid & 3) * 4;       // 0,4,8,12
    const float* Ag = A + (size_t)(bm + ldRow) * K + ldCol;
    const float* Bg = B + (size_t)(bn + ldRow) * K + ldCol;
    const size_t rowskip = (size_t)64 * K;

    float acc[2][8][4];
#pragma unroll
    for (int mi = 0; mi < 2; mi++)
#pragma unroll
        for (int ni = 0; ni < 8; ni++)
#pragma unroll
            for (int e = 0; e < 4; e++) acc[mi][ni][e] = 0.0f;

    float4 av0, av1, bv0, bv1;

    // prologue: load+store tile 0
    av0 = *(const float4*)(Ag);
    av1 = *(const float4*)(Ag + rowskip);
    bv0 = *(const float4*)(Bg);
    bv1 = *(const float4*)(Bg + rowskip);
#pragma unroll
    for (int e = 0; e < 4; e++) {
        As[0][ldCol + e][ldRow]      = f2tf32(((const float*)&av0)[e]);
        As[0][ldCol + e][ldRow + 64] = f2tf32(((const float*)&av1)[e]);
        Bs[0][ldCol + e][ldRow]      = f2tf32(((const float*)&bv0)[e]);
        Bs[0][ldCol + e][ldRow + 64] = f2tf32(((const float*)&bv1)[e]);
    }
    __syncthreads();

    int p = 0;
    for (int k0 = 0; k0 < K; k0 += BK) {
        const bool has_next = (k0 + BK) < K;
        if (has_next) {
            av0 = *(const float4*)(Ag + k0 + BK);
            av1 = *(const float4*)(Ag + rowskip + k0 + BK);
            bv0 = *(const float4*)(Bg + k0 + BK);
            bv1 = *(const float4*)(Bg + rowskip + k0 + BK);
        }

#pragma unroll
        for (int kk = 0; kk < BK; kk += 8) {
            unsigned afr[2][4];
#pragma unroll
            for (int mi = 0; mi < 2; mi++) {
                const int m = moff + 16 * mi + g;
                afr[mi][0] = As[p][kk + t][m];
                afr[mi][1] = As[p][kk + t][m + 8];
                afr[mi][2] = As[p][kk + t + 4][m];
                afr[mi][3] = As[p][kk + t + 4][m + 8];
            }
            unsigned bfr[8][2];
#pragma unroll
            for (int ni = 0; ni < 8; ni++) {
                const int n = noff + 8 * ni + g;
                bfr[ni][0] = Bs[p][kk + t][n];
                bfr[ni][1] = Bs[p][kk + t + 4][n];
            }
#pragma unroll
            for (int mi = 0; mi < 2; mi++)
#pragma unroll
                for (int ni = 0; ni < 8; ni++)
                    mma_tf32(acc[mi][ni], afr[mi], bfr[ni]);
        }

        if (has_next) {
            const int q = 1 - p;
#pragma unroll
            for (int e = 0; e < 4; e++) {
                As[q][ldCol + e][ldRow]      = f2tf32(((const float*)&av0)[e]);
                As[q][ldCol + e][ldRow + 64] = f2tf32(((const float*)&av1)[e]);
                Bs[q][ldCol + e][ldRow]      = f2tf32(((const float*)&bv0)[e]);
                Bs[q][ldCol + e][ldRow + 64] = f2tf32(((const float*)&bv1)[e]);
            }
        }
        __syncthreads();
        p ^= 1;
    }

    // epilogue: per atom, rows (r0, r0+8), cols (c, c+1)
#pragma unroll
    for (int mi = 0; mi < 2; mi++) {
        const int r0 = bm + moff + 16 * mi + g;
#pragma unroll
        for (int ni = 0; ni < 8; ni++) {
            const int c = bn + noff + 8 * ni + 2 * t;
            float v00 = acc[mi][ni][0], v01 = acc[mi][ni][1];
            float v10 = acc[mi][ni][2], v11 = acc[mi][ni][3];
            if (MODE == 1) {
                const float b0 = bias[c], b1 = bias[c + 1];
                v00 = gelu_exact(v00 + b0); v01 = gelu_exact(v01 + b1);
                v10 = gelu_exact(v10 + b0); v11 = gelu_exact(v11 + b1);
            } else if (MODE == 2) {
                if (bias) {
                    const float b0 = bias[c], b1 = bias[c + 1];
                    v00 += b0; v01 += b1; v10 += b0; v11 += b1;
                }
                const float2 rr0 = *(const float2*)(resid + (size_t)r0 * N + c);
                const float2 rr1 = *(const float2*)(resid + (size_t)(r0 + 8) * N + c);
                v00 += rr0.x; v01 += rr0.y; v10 += rr1.x; v11 += rr1.y;
            }
            float2 o0; o0.x = v00; o0.y = v01;
            float2 o1; o1.x = v10; o1.y = v11;
            *(float2*)(C + (size_t)r0 * N + c) = o0;
            *(float2*)(C + (size_t)(r0 + 8) * N + c) = o1;
        }
    }
}

// ---------------------------------------------------------------------------
// Embedding gather
// ---------------------------------------------------------------------------
__global__ void embed_kernel(const int* __restrict__ ids,
                             const float* __restrict__ emb,
                             float* __restrict__ x)
{
    const int row = blockIdx.x;
    const int id = ids[row];
    const float4* src = (const float4*)(emb + (size_t)id * DMODEL);
    float4* dst = (float4*)(x + (size_t)row * DMODEL);
    dst[threadIdx.x] = src[threadIdx.x];
}

// ---------------------------------------------------------------------------
// LayerNorm
// ---------------------------------------------------------------------------
__global__ __launch_bounds__(256)
void layernorm_kernel(const float* __restrict__ x, const float* __restrict__ w,
                      const float* __restrict__ b, float* __restrict__ y)
{
    const int row = blockIdx.x;
    const int tid = threadIdx.x;
    __shared__ float red[256];

    float4 v = ((const float4*)(x + (size_t)row * DMODEL))[tid];
    float s = v.x + v.y + v.z + v.w;
    red[tid] = s; __syncthreads();
    for (int k = 128; k > 0; k >>= 1) {
        if (tid < k) red[tid] += red[tid + k];
        __syncthreads();
    }
    const float mu = red[0] * (1.0f / DMODEL);
    __syncthreads();

    float dx = v.x - mu, dy = v.y - mu, dz = v.z - mu, dw = v.w - mu;
    s = dx * dx + dy * dy + dz * dz + dw * dw;
    red[tid] = s; __syncthreads();
    for (int k = 128; k > 0; k >>= 1) {
        if (tid < k) red[tid] += red[tid + k];
        __syncthreads();
    }
    const float rstd = rsqrtf(red[0] * (1.0f / DMODEL) + 1e-5f);

    float4 wv = ((const float4*)w)[tid];
    float4 bv = ((const float4*)b)[tid];
    float4 o;
    o.x = dx * rstd * wv.x + bv.x;
    o.y = dy * rstd * wv.y + bv.y;
    o.z = dz * rstd * wv.z + bv.z;
    o.w = dw * rstd * wv.w + bv.w;
    ((float4*)(y + (size_t)row * DMODEL))[tid] = o;
}

// ---------------------------------------------------------------------------
// RoPE in-place on q,k halves of u
// ---------------------------------------------------------------------------
__global__ __launch_bounds__(256)
void rope_kernel(float* __restrict__ u)
{
    const int idx = blockIdx.x * 256 + threadIdx.x;
    const int row = idx >> 10;
    const int j = idx & 1023;
    const int s = row & (SEQ - 1);
    const int which = j >> 9;        // 0 = q, 1 = k
    const int pp = j & 511;
    const int head = pp >> 5;
    const int i = pp & 31;

    const float inv = exp2f(-(float)(2 * i) * (1.0f / 64.0f) * 13.287712379549449f);
    const float ang = (float)s * inv;
    float sn, cs;
    sincosf(ang, &sn, &cs);

    const size_t off = (size_t)row * (3 * TDIM) + (size_t)which * TDIM + head * HDIM + i;
    const float v0 = u[off];
    const float v1 = u[off + 32];
    u[off]      = v0 * cs - v1 * sn;
    u[off + 32] = v1 * cs + v0 * sn;
}

// ---------------------------------------------------------------------------
// Attention v2: flash-style, 8 queries per block (warp per query),
// online softmax, K/V staged in smem 64-row chunks (8x reuse).
// grid = (SEQ/8, NHEAD, BATCH), 256 threads.
// ---------------------------------------------------------------------------
#define QT 8
__global__ __launch_bounds__(256)
void attn_kernel(const float* __restrict__ u, float* __restrict__ out)
{
    const int q0 = blockIdx.x * QT;
    const int h  = blockIdx.y;
    const int b  = blockIdx.z;
    const int tid  = threadIdx.x;
    const int warp = tid >> 5;
    const int lane = tid & 31;
    const int q = q0 + warp;

    __shared__ float sq [QT][HDIM];      // 2 KB
    __shared__ float ksm[64][65];        // 16.25 KB + pad
    __shared__ float vsm[64][65];

    const size_t rowbase = (size_t)(b * SEQ) * (3 * TDIM);

    // load Q tile
    for (int i = tid; i < QT * HDIM; i += 256) {
        const int r = i >> 6, c = i & 63;
        sq[r][c] = u[rowbase + (size_t)(q0 + r) * (3 * TDIM) + h * HDIM + c];
    }
    __syncthreads();

    // hoist q row into registers (broadcast LDS once)
    float qreg[HDIM];
#pragma unroll
    for (int j = 0; j < HDIM; j++) qreg[j] = sq[warp][j];

    float m = -1e30f, l = 0.0f, a0 = 0.0f, a1 = 0.0f;
    const int nkmax = q0 + QT;

    for (int c0 = 0; c0 < nkmax; c0 += 64) {
        // load K and V chunks: 64 rows x 64 floats each
        for (int i4 = tid; i4 < 1024; i4 += 256) {
            const int r = i4 >> 4;
            const int c = (i4 & 15) * 4;
            const size_t base = rowbase + (size_t)(c0 + r) * (3 * TDIM) + h * HDIM + c;
            const float4 kv = *(const float4*)(u + base + TDIM);
            const float4 vv = *(const float4*)(u + base + 2 * TDIM);
            ksm[r][c + 0] = kv.x; ksm[r][c + 1] = kv.y;
            ksm[r][c + 2] = kv.z; ksm[r][c + 3] = kv.w;
            vsm[r][c + 0] = vv.x; vsm[r][c + 1] = vv.y;
            vsm[r][c + 2] = vv.z; vsm[r][c + 3] = vv.w;
        }
        __syncthreads();

        // scores for rows (c0+lane) and (c0+lane+32)
        float d0 = 0.0f, d1 = 0.0f;
#pragma unroll
        for (int j = 0; j < HDIM; j++) {
            d0 = fmaf(qreg[j], ksm[lane][j], d0);
            d1 = fmaf(qreg[j], ksm[lane + 32][j], d1);
        }
        d0 *= 0.125f; d1 *= 0.125f;
        const float s0 = (c0 + lane      <= q) ? d0 : -1e30f;
        const float s1 = (c0 + lane + 32 <= q) ? d1 : -1e30f;

        float cmax = fmaxf(s0, s1);
#pragma unroll
        for (int off = 16; off > 0; off >>= 1)
            cmax = fmaxf(cmax, __shfl_xor_sync(0xffffffff, cmax, off));

        const float mnew  = fmaxf(m, cmax);
        const float scale = __expf(m - mnew);
        const float p0 = __expf(s0 - mnew);
        const float p1 = __expf(s1 - mnew);
        l = l * scale + p0 + p1;
        a0 *= scale; a1 *= scale;

#pragma unroll 8
        for (int r = 0; r < 32; r++) {
            const float pr = __shfl_sync(0xffffffff, p0, r);
            a0 = fmaf(pr, vsm[r][lane], a0);
            a1 = fmaf(pr, vsm[r][lane + 32], a1);
        }
#pragma unroll 8
        for (int r = 0; r < 32; r++) {
            const float pr = __shfl_sync(0xffffffff, p1, r);
            a0 = fmaf(pr, vsm[r + 32][lane], a0);
            a1 = fmaf(pr, vsm[r + 32][lane + 32], a1);
        }
        m = mnew;
        __syncthreads();
    }

#pragma unroll
    for (int off = 16; off > 0; off >>= 1)
        l += __shfl_xor_sync(0xffffffff, l, off);
    const float inv = 1.0f / l;

    out[(size_t)(b * SEQ + q) * TDIM + h * HDIM + lane]      = a0 * inv;
    out[(size_t)(b * SEQ + q) * TDIM + h * HDIM + lane + 32] = a1 * inv;
}

// ---------------------------------------------------------------------------
// Host orchestration
// ---------------------------------------------------------------------------
extern "C" void kernel_launch(void* const* d_in, const int* in_sizes, int n_in,
                              void* d_out, int out_size)
{
    (void)in_sizes; (void)n_in; (void)out_size;

    const int*   ids = (const int*)  d_in[0];
    const float* emb = (const float*)d_in[1];
    const float* Wu  = (const float*)d_in[2];
    const float* Wo  = (const float*)d_in[3];
    const float* n1w = (const float*)d_in[4];
    const float* n1b = (const float*)d_in[5];
    const float* n2w = (const float*)d_in[6];
    const float* n2b = (const float*)d_in[7];
    const float* f1w = (const float*)d_in[8];
    const float* f1b = (const float*)d_in[9];
    const float* f2w = (const float*)d_in[10];
    const float* f2b = (const float*)d_in[11];
    const float* fnw = (const float*)d_in[12];
    const float* fnb = (const float*)d_in[13];
    float* out = (float*)d_out;

    float *x, *xn, *u, *attn, *hbuf;
    cudaGetSymbolAddress((void**)&x,    g_x);
    cudaGetSymbolAddress((void**)&xn,   g_xn);
    cudaGetSymbolAddress((void**)&u,    g_u);
    cudaGetSymbolAddress((void**)&attn, g_attn);
    cudaGetSymbolAddress((void**)&hbuf, g_h);

    embed_kernel<<<NROWS, 256>>>(ids, emb, x);

    for (int l = 0; l < NLAYER; l++) {
        const float* Wu_l  = Wu  + (size_t)l * 3 * TDIM * DMODEL;
        const float* Wo_l  = Wo  + (size_t)l * DMODEL * TDIM;
        const float* f1w_l = f1w + (size_t)l * FFDIM * DMODEL;
        const float* f1b_l = f1b + (size_t)l * FFDIM;
        const float* f2w_l = f2w + (size_t)l * DMODEL * FFDIM;
        const float* f2b_l = f2b + (size_t)l * DMODEL;

        layernorm_kernel<<<NROWS, 256>>>(x, n1w + l * DMODEL, n1b + l * DMODEL, xn);

        gemm_mma<0><<<dim3(3 * TDIM / 128, NROWS / 128), 256>>>(
            xn, Wu_l, nullptr, nullptr, u, NROWS, 3 * TDIM, DMODEL);

        rope_kernel<<<(NROWS * 1024) / 256, 256>>>(u);

        attn_kernel<<<dim3(SEQ / QT, NHEAD, BATCH), 256>>>(u, attn);

        gemm_mma<2><<<dim3(DMODEL / 128, NROWS / 128), 256>>>(
            attn, Wo_l, nullptr, x, x, NROWS, DMODEL, TDIM);

        layernorm_kernel<<<NROWS, 256>>>(x, n2w + l * DMODEL, n2b + l * DMODEL, xn);

        gemm_mma<1><<<dim3(FFDIM / 128, NROWS / 128), 256>>>(
            xn, f1w_l, f1b_l, nullptr, hbuf, NROWS, FFDIM, DMODEL);

        gemm_mma<2><<<dim3(DMODEL / 128, NROWS / 128), 256>>>(
            hbuf, f2w_l, f2b_l, x, x, NROWS, DMODEL, FFDIM);
    }

    layernorm_kernel<<<NROWS, 256>>>(x, fnw, fnb, xn);

    gemm_mma<0><<<dim3(VOCAB / 128, NROWS / 128), 256>>>(
        xn, emb, nullptr, nullptr, out, NROWS, VOCAB, DMODEL);
}

// round 5
// speedup vs baseline: 1.1966x; 1.1966x over previous
#include <cuda_runtime.h>
#include <cuda_fp16.h>
#include <math.h>

#define BATCH   2
#define SEQ     1024
#define NROWS   (BATCH * SEQ)
#define DMODEL  1024
#define NHEAD   16
#define HDIM    64
#define TDIM    1024
#define FFDIM   4096
#define NLAYER  8
#define VOCAB   32000

__device__ float g_x   [NROWS * DMODEL];
__device__ float g_xn  [NROWS * DMODEL];
__device__ float g_u   [NROWS * 3 * TDIM];
__device__ float g_attn[NROWS * TDIM];
__device__ float g_h   [NROWS * FFDIM];

__device__ __forceinline__ float gelu_exact(float v) {
    return 0.5f * v * (1.0f + erff(v * 0.70710678118654752440f));
}

__device__ __forceinline__ unsigned packh2(float a, float b) {
    __half2 h = __floats2half2_rn(a, b);
    return *(unsigned*)&h;
}

__device__ __forceinline__ void mma_f16(float* c, const unsigned* a, const unsigned* b) {
    asm volatile(
        "mma.sync.aligned.m16n8k16.row.col.f32.f16.f16.f32 "
        "{%0,%1,%2,%3},{%4,%5,%6,%7},{%8,%9},{%0,%1,%2,%3};"
        : "+f"(c[0]), "+f"(c[1]), "+f"(c[2]), "+f"(c[3])
        : "r"(a[0]), "r"(a[1]), "r"(a[2]), "r"(a[3]), "r"(b[0]), "r"(b[1]));
}

// ---------------------------------------------------------------------------
// fp16 tensor-core GEMM: C[M,N] = A[M,K] @ B[N,K]^T  (+ epilogue)
// MODE 0: plain   MODE 1: gelu(acc+bias)   MODE 2: resid + acc (+bias)
// Tile 128x128, BK=16 (one k16 mma group), double-buffered smem.
// smem: [kpair 0..7][row 0..127] packed half2 along k, LD=132 (CF banks).
// ---------------------------------------------------------------------------
template<int MODE>
__global__ __launch_bounds__(256)
void gemm_f16(const float* __restrict__ A, const float* __restrict__ B,
              const float* __restrict__ bias, const float* __restrict__ resid,
              float* __restrict__ C, int M, int N, int K)
{
    constexpr int LD = 132;
    __shared__ unsigned As[2][8][LD];
    __shared__ unsigned Bs[2][8][LD];

    const int bm = blockIdx.y * 128;
    const int bn = blockIdx.x * 128;
    const int tid  = threadIdx.x;
    const int warp = tid >> 5;
    const int lane = tid & 31;
    const int g = lane >> 2;
    const int t = lane & 3;
    const int moff = (warp & 3) * 32;
    const int noff = (warp >> 2) * 64;

    const int ldRow = tid >> 2;           // 0..63 (+64)
    const int ldCol = (tid & 3) * 4;      // 0,4,8,12
    const int kp0 = ldCol >> 1;           // 0,2,4,6
    const float* Ag = A + (size_t)(bm + ldRow) * K + ldCol;
    const float* Bg = B + (size_t)(bn + ldRow) * K + ldCol;
    const size_t rowskip = (size_t)64 * K;

    float acc[2][8][4];
#pragma unroll
    for (int mi = 0; mi < 2; mi++)
#pragma unroll
        for (int ni = 0; ni < 8; ni++)
#pragma unroll
            for (int e = 0; e < 4; e++) acc[mi][ni][e] = 0.0f;

    float4 av0, av1, bv0, bv1;
    av0 = *(const float4*)(Ag);
    av1 = *(const float4*)(Ag + rowskip);
    bv0 = *(const float4*)(Bg);
    bv1 = *(const float4*)(Bg + rowskip);
    As[0][kp0    ][ldRow]      = packh2(av0.x, av0.y);
    As[0][kp0 + 1][ldRow]      = packh2(av0.z, av0.w);
    As[0][kp0    ][ldRow + 64] = packh2(av1.x, av1.y);
    As[0][kp0 + 1][ldRow + 64] = packh2(av1.z, av1.w);
    Bs[0][kp0    ][ldRow]      = packh2(bv0.x, bv0.y);
    Bs[0][kp0 + 1][ldRow]      = packh2(bv0.z, bv0.w);
    Bs[0][kp0    ][ldRow + 64] = packh2(bv1.x, bv1.y);
    Bs[0][kp0 + 1][ldRow + 64] = packh2(bv1.z, bv1.w);
    __syncthreads();

    int p = 0;
    for (int k0 = 0; k0 < K; k0 += 16) {
        const bool nxt = (k0 + 16) < K;
        if (nxt) {
            av0 = *(const float4*)(Ag + k0 + 16);
            av1 = *(const float4*)(Ag + rowskip + k0 + 16);
            bv0 = *(const float4*)(Bg + k0 + 16);
            bv1 = *(const float4*)(Bg + rowskip + k0 + 16);
        }

        unsigned afr[2][4];
#pragma unroll
        for (int mi = 0; mi < 2; mi++) {
            const int m = moff + 16 * mi + g;
            afr[mi][0] = As[p][t][m];
            afr[mi][1] = As[p][t][m + 8];
            afr[mi][2] = As[p][t + 4][m];
            afr[mi][3] = As[p][t + 4][m + 8];
        }
        unsigned bfr[8][2];
#pragma unroll
        for (int ni = 0; ni < 8; ni++) {
            const int n = noff + 8 * ni + g;
            bfr[ni][0] = Bs[p][t][n];
            bfr[ni][1] = Bs[p][t + 4][n];
        }
#pragma unroll
        for (int mi = 0; mi < 2; mi++)
#pragma unroll
            for (int ni = 0; ni < 8; ni++)
                mma_f16(acc[mi][ni], afr[mi], bfr[ni]);

        if (nxt) {
            const int q = 1 - p;
            As[q][kp0    ][ldRow]      = packh2(av0.x, av0.y);
            As[q][kp0 + 1][ldRow]      = packh2(av0.z, av0.w);
            As[q][kp0    ][ldRow + 64] = packh2(av1.x, av1.y);
            As[q][kp0 + 1][ldRow + 64] = packh2(av1.z, av1.w);
            Bs[q][kp0    ][ldRow]      = packh2(bv0.x, bv0.y);
            Bs[q][kp0 + 1][ldRow]      = packh2(bv0.z, bv0.w);
            Bs[q][kp0    ][ldRow + 64] = packh2(bv1.x, bv1.y);
            Bs[q][kp0 + 1][ldRow + 64] = packh2(bv1.z, bv1.w);
        }
        __syncthreads();
        p ^= 1;
    }

#pragma unroll
    for (int mi = 0; mi < 2; mi++) {
        const int r0 = bm + moff + 16 * mi + g;
#pragma unroll
        for (int ni = 0; ni < 8; ni++) {
            const int c = bn + noff + 8 * ni + 2 * t;
            float v00 = acc[mi][ni][0], v01 = acc[mi][ni][1];
            float v10 = acc[mi][ni][2], v11 = acc[mi][ni][3];
            if (MODE == 1) {
                const float b0 = bias[c], b1 = bias[c + 1];
                v00 = gelu_exact(v00 + b0); v01 = gelu_exact(v01 + b1);
                v10 = gelu_exact(v10 + b0); v11 = gelu_exact(v11 + b1);
            } else if (MODE == 2) {
                if (bias) {
                    const float b0 = bias[c], b1 = bias[c + 1];
                    v00 += b0; v01 += b1; v10 += b0; v11 += b1;
                }
                const float2 rr0 = *(const float2*)(resid + (size_t)r0 * N + c);
                const float2 rr1 = *(const float2*)(resid + (size_t)(r0 + 8) * N + c);
                v00 += rr0.x; v01 += rr0.y; v10 += rr1.x; v11 += rr1.y;
            }
            float2 o0; o0.x = v00; o0.y = v01;
            float2 o1; o1.x = v10; o1.y = v11;
            *(float2*)(C + (size_t)r0 * N + c) = o0;
            *(float2*)(C + (size_t)(r0 + 8) * N + c) = o1;
        }
    }
}

__global__ void embed_kernel(const int* __restrict__ ids,
                             const float* __restrict__ emb,
                             float* __restrict__ x)
{
    ((float4*)(x + (size_t)blockIdx.x * DMODEL))[threadIdx.x] =
        ((const float4*)(emb + (size_t)ids[blockIdx.x] * DMODEL))[threadIdx.x];
}

__global__ __launch_bounds__(256)
void layernorm_kernel(const float* __restrict__ x, const float* __restrict__ w,
                      const float* __restrict__ b, float* __restrict__ y)
{
    const int row = blockIdx.x;
    const int tid = threadIdx.x;
    __shared__ float red[256];

    float4 v = ((const float4*)(x + (size_t)row * DMODEL))[tid];
    float s = v.x + v.y + v.z + v.w;
    red[tid] = s; __syncthreads();
    for (int k = 128; k > 0; k >>= 1) {
        if (tid < k) red[tid] += red[tid + k];
        __syncthreads();
    }
    const float mu = red[0] * (1.0f / DMODEL);
    __syncthreads();

    const float dx = v.x - mu, dy = v.y - mu, dz = v.z - mu, dw = v.w - mu;
    red[tid] = dx * dx + dy * dy + dz * dz + dw * dw; __syncthreads();
    for (int k = 128; k > 0; k >>= 1) {
        if (tid < k) red[tid] += red[tid + k];
        __syncthreads();
    }
    const float rstd = rsqrtf(red[0] * (1.0f / DMODEL) + 1e-5f);

    const float4 wv = ((const float4*)w)[tid];
    const float4 bv = ((const float4*)b)[tid];
    float4 o;
    o.x = dx * rstd * wv.x + bv.x;
    o.y = dy * rstd * wv.y + bv.y;
    o.z = dz * rstd * wv.z + bv.z;
    o.w = dw * rstd * wv.w + bv.w;
    ((float4*)(y + (size_t)row * DMODEL))[tid] = o;
}

__global__ __launch_bounds__(256)
void rope_kernel(float* __restrict__ u)
{
    const int idx = blockIdx.x * 256 + threadIdx.x;
    const int row = idx >> 10;
    const int j = idx & 1023;
    const int s = row & (SEQ - 1);
    const int which = j >> 9;
    const int pp = j & 511;
    const int head = pp >> 5;
    const int i = pp & 31;

    const float inv = exp2f(-(float)(2 * i) * (1.0f / 64.0f) * 13.287712379549449f);
    float sn, cs;
    sincosf((float)s * inv, &sn, &cs);

    const size_t off = (size_t)row * (3 * TDIM) + (size_t)which * TDIM + head * HDIM + i;
    const float v0 = u[off];
    const float v1 = u[off + 32];
    u[off]      = v0 * cs - v1 * sn;
    u[off + 32] = v1 * cs + v0 * sn;
}

#define QT 8
__global__ __launch_bounds__(256)
void attn_kernel(const float* __restrict__ u, float* __restrict__ out)
{
    const int q0 = blockIdx.x * QT;
    const int h  = blockIdx.y;
    const int b  = blockIdx.z;
    const int tid  = threadIdx.x;
    const int warp = tid >> 5;
    const int lane = tid & 31;
    const int q = q0 + warp;

    __shared__ float sq [QT][HDIM];
    __shared__ float ksm[64][65];
    __shared__ float vsm[64][65];

    const size_t rb = (size_t)(b * SEQ) * (3 * TDIM);

    for (int i = tid; i < QT * HDIM; i += 256)
        sq[i >> 6][i & 63] = u[rb + (size_t)(q0 + (i >> 6)) * (3 * TDIM) + h * HDIM + (i & 63)];
    __syncthreads();

    float qr[HDIM];
#pragma unroll
    for (int j = 0; j < HDIM; j++) qr[j] = sq[warp][j];

    float m = -1e30f, l = 0.0f, a0 = 0.0f, a1 = 0.0f;

    for (int c0 = 0; c0 < q0 + QT; c0 += 64) {
        for (int i4 = tid; i4 < 1024; i4 += 256) {
            const int r = i4 >> 4;
            const int c = (i4 & 15) * 4;
            const size_t base = rb + (size_t)(c0 + r) * (3 * TDIM) + h * HDIM + c;
            const float4 kv = *(const float4*)(u + base + TDIM);
            const float4 vv = *(const float4*)(u + base + 2 * TDIM);
            ksm[r][c] = kv.x; ksm[r][c + 1] = kv.y; ksm[r][c + 2] = kv.z; ksm[r][c + 3] = kv.w;
            vsm[r][c] = vv.x; vsm[r][c + 1] = vv.y; vsm[r][c + 2] = vv.z; vsm[r][c + 3] = vv.w;
        }
        __syncthreads();

        float d0 = 0.0f, d1 = 0.0f;
#pragma unroll
        for (int j = 0; j < HDIM; j++) {
            d0 = fmaf(qr[j], ksm[lane][j], d0);
            d1 = fmaf(qr[j], ksm[lane + 32][j], d1);
        }
        d0 *= 0.125f; d1 *= 0.125f;
        const float s0 = (c0 + lane      <= q) ? d0 : -1e30f;
        const float s1 = (c0 + lane + 32 <= q) ? d1 : -1e30f;

        float cm = fmaxf(s0, s1);
#pragma unroll
        for (int o = 16; o > 0; o >>= 1) cm = fmaxf(cm, __shfl_xor_sync(0xffffffff, cm, o));

        const float mn = fmaxf(m, cm);
        const float sc = __expf(m - mn);
        const float p0 = __expf(s0 - mn);
        const float p1 = __expf(s1 - mn);
        l = l * sc + p0 + p1;
        a0 *= sc; a1 *= sc;

#pragma unroll 8
        for (int r = 0; r < 32; r++) {
            const float pr = __shfl_sync(0xffffffff, p0, r);
            a0 = fmaf(pr, vsm[r][lane], a0);
            a1 = fmaf(pr, vsm[r][lane + 32], a1);
        }
#pragma unroll 8
        for (int r = 0; r < 32; r++) {
            const float pr = __shfl_sync(0xffffffff, p1, r);
            a0 = fmaf(pr, vsm[r + 32][lane], a0);
            a1 = fmaf(pr, vsm[r + 32][lane + 32], a1);
        }
        m = mn;
        __syncthreads();
    }

#pragma unroll
    for (int o = 16; o > 0; o >>= 1) l += __shfl_xor_sync(0xffffffff, l, o);
    const float inv = 1.0f / l;

    out[(size_t)(b * SEQ + q) * TDIM + h * HDIM + lane]      = a0 * inv;
    out[(size_t)(b * SEQ + q) * TDIM + h * HDIM + lane + 32] = a1 * inv;
}

extern "C" void kernel_launch(void* const* d_in, const int* in_sizes, int n_in,
                              void* d_out, int out_size)
{
    (void)in_sizes; (void)n_in; (void)out_size;

    const int*   ids = (const int*)  d_in[0];
    const float* emb = (const float*)d_in[1];
    const float* Wu  = (const float*)d_in[2];
    const float* Wo  = (const float*)d_in[3];
    const float* n1w = (const float*)d_in[4];
    const float* n1b = (const float*)d_in[5];
    const float* n2w = (const float*)d_in[6];
    const float* n2b = (const float*)d_in[7];
    const float* f1w = (const float*)d_in[8];
    const float* f1b = (const float*)d_in[9];
    const float* f2w = (const float*)d_in[10];
    const float* f2b = (const float*)d_in[11];
    const float* fnw = (const float*)d_in[12];
    const float* fnb = (const float*)d_in[13];
    float* out = (float*)d_out;

    float *x, *xn, *u, *attn, *hbuf;
    cudaGetSymbolAddress((void**)&x,    g_x);
    cudaGetSymbolAddress((void**)&xn,   g_xn);
    cudaGetSymbolAddress((void**)&u,    g_u);
    cudaGetSymbolAddress((void**)&attn, g_attn);
    cudaGetSymbolAddress((void**)&hbuf, g_h);

    embed_kernel<<<NROWS, 256>>>(ids, emb, x);

    for (int l = 0; l < NLAYER; l++) {
        const float* Wu_l  = Wu  + (size_t)l * 3 * TDIM * DMODEL;
        const float* Wo_l  = Wo  + (size_t)l * DMODEL * TDIM;
        const float* f1w_l = f1w + (size_t)l * FFDIM * DMODEL;
        const float* f1b_l = f1b + (size_t)l * FFDIM;
        const float* f2w_l = f2w + (size_t)l * DMODEL * FFDIM;
        const float* f2b_l = f2b + (size_t)l * DMODEL;

        layernorm_kernel<<<NROWS, 256>>>(x, n1w + l * DMODEL, n1b + l * DMODEL, xn);

        gemm_f16<0><<<dim3(3 * TDIM / 128, NROWS / 128), 256>>>(
            xn, Wu_l, nullptr, nullptr, u, NROWS, 3 * TDIM, DMODEL);

        rope_kernel<<<(NROWS * 1024) / 256, 256>>>(u);

        attn_kernel<<<dim3(SEQ / QT, NHEAD, BATCH), 256>>>(u, attn);

        gemm_f16<2><<<dim3(DMODEL / 128, NROWS / 128), 256>>>(
            attn, Wo_l, nullptr, x, x, NROWS, DMODEL, TDIM);

        layernorm_kernel<<<NROWS, 256>>>(x, n2w + l * DMODEL, n2b + l * DMODEL, xn);

        gemm_f16<1><<<dim3(FFDIM / 128, NROWS / 128), 256>>>(
            xn, f1w_l, f1b_l, nullptr, hbuf, NROWS, FFDIM, DMODEL);

        gemm_f16<2><<<dim3(DMODEL / 128, NROWS / 128), 256>>>(
            hbuf, f2w_l, f2b_l, x, x, NROWS, DMODEL, FFDIM);
    }

    layernorm_kernel<<<NROWS, 256>>>(x, fnw, fnb, xn);

    gemm_f16<0><<<dim3(VOCAB / 128, NROWS / 128), 256>>>(
        xn, emb, nullptr, nullptr, out, NROWS, VOCAB, DMODEL);
}

// round 6
// speedup vs baseline: 1.6663x; 1.3925x over previous
#include <cuda_runtime.h>
#include <cuda_fp16.h>
#include <math.h>
#include <stdint.h>

#define BATCH   2
#define SEQ     1024
#define NROWS   (BATCH * SEQ)
#define DMODEL  1024
#define NHEAD   16
#define HDIM    64
#define TDIM    1024
#define FFDIM   4096
#define NLAYER  8
#define VOCAB   32000

// fp16 weight pool offsets (halves)
#define WU16  0
#define WO16  25165824u               // 8*3*1024*1024
#define F116  33554432u               // WO16 + 8*1024*1024
#define F216  67108864u               // F116 + 8*4096*1024
#define EMB16 100663296u              // F216 + 8*4096*1024
#define W16_TOTAL 133431296u          // EMB16 + 32000*1024

__device__ float  g_x [NROWS * DMODEL];
__device__ float  g_u [NROWS * 3 * TDIM];
__device__ __half g_xn16[NROWS * DMODEL];
__device__ __half g_at16[NROWS * TDIM];
__device__ __half g_h16 [NROWS * FFDIM];
__device__ __half g_w16 [W16_TOTAL];

__device__ __forceinline__ float gelu_exact(float v) {
    return 0.5f * v * (1.0f + erff(v * 0.70710678118654752440f));
}
__device__ __forceinline__ uint32_t s2u(const void* p) {
    uint32_t a;
    asm("{ .reg .u64 t; cvta.to.shared.u64 t, %1; cvt.u32.u64 %0, t; }" : "=r"(a) : "l"(p));
    return a;
}
__device__ __forceinline__ void cp16(uint32_t s, const void* g) {
    asm volatile("cp.async.cg.shared.global [%0], [%1], 16;" :: "r"(s), "l"(g));
}
__device__ __forceinline__ void ldsm4(unsigned* r, uint32_t a) {
    asm volatile("ldmatrix.sync.aligned.m8n8.x4.shared.b16 {%0,%1,%2,%3}, [%4];"
        : "=r"(r[0]), "=r"(r[1]), "=r"(r[2]), "=r"(r[3]) : "r"(a));
}
__device__ __forceinline__ void mma_f16(float* c, const unsigned* a, const unsigned* b) {
    asm volatile(
        "mma.sync.aligned.m16n8k16.row.col.f32.f16.f16.f32 "
        "{%0,%1,%2,%3},{%4,%5,%6,%7},{%8,%9},{%0,%1,%2,%3};"
        : "+f"(c[0]), "+f"(c[1]), "+f"(c[2]), "+f"(c[3])
        : "r"(a[0]), "r"(a[1]), "r"(a[2]), "r"(a[3]), "r"(b[0]), "r"(b[1]));
}

// ---------------------------------------------------------------------------
// fp16 GEMM: C[M,N] = A[M,K] @ B[N,K]^T  (+ epilogue)
// MODE 0: fp32 C   MODE 1: gelu(acc+bias) -> fp16 C16   MODE 2: acc(+bias)+resid -> fp32
// BM=BN=128, BK=32, 3-stage cp.async pipeline, ldmatrix fragment feeds.
// smem rows 80B stride (32 halves + 8 pad) -> conflict-free LDSM & cp.async.
// ---------------------------------------------------------------------------
template<int MODE>
__global__ __launch_bounds__(256)
void gemm_f16(const __half* __restrict__ A, const __half* __restrict__ B,
              const float* __restrict__ bias, const float* __restrict__ resid,
              float* __restrict__ C, __half* __restrict__ C16, int N, int K)
{
    extern __shared__ __align__(128) char smem[];
    const uint32_t sb = s2u(smem);
    const int tid = threadIdx.x, warp = tid >> 5, lane = tid & 31;
    const int bm = blockIdx.y * 128, bn = blockIdx.x * 128;
    const int moff = (warp & 3) * 32, noff = (warp >> 2) * 64;
    const int g = lane >> 2, t = lane & 3;
    const int nk = K >> 5;
    const int lrow = tid >> 2, lc = tid & 3;

    float acc[2][8][4];
#pragma unroll
    for (int mi = 0; mi < 2; mi++)
#pragma unroll
        for (int ni = 0; ni < 8; ni++)
#pragma unroll
            for (int e = 0; e < 4; e++) acc[mi][ni][e] = 0.0f;

#define LOADSTAGE(st, ks) do { \
    const uint32_t so = sb + (uint32_t)(st) * 20480u; \
    const int kb = (ks) * 32; \
    const __half* gA = A + (size_t)(bm + lrow) * K + kb + lc * 8; \
    const __half* gB = B + (size_t)(bn + lrow) * K + kb + lc * 8; \
    const uint32_t sA = so + lrow * 80 + lc * 16; \
    const uint32_t sB = so + 10240u + lrow * 80 + lc * 16; \
    cp16(sA, gA); cp16(sB, gB); \
    cp16(sA + 64 * 80, gA + (size_t)64 * K); \
    cp16(sB + 64 * 80, gB + (size_t)64 * K); \
} while (0)

    LOADSTAGE(0, 0);
    asm volatile("cp.async.commit_group;" ::: "memory");
    LOADSTAGE(1, 1);
    asm volatile("cp.async.commit_group;" ::: "memory");

    // fragment base addresses (stage-relative)
    const uint32_t aoff = (uint32_t)((moff + (lane & 15)) * 80 + ((lane >> 4) & 1) * 16);
    const uint32_t boff = 10240u +
        (uint32_t)((noff + (lane & 7) + ((lane >> 4) & 1) * 8) * 80 + ((lane >> 3) & 1) * 16);

    for (int ks = 0; ks < nk; ks++) {
        asm volatile("cp.async.wait_group %0;" :: "n"(1) : "memory");
        __syncthreads();
        const int st = ks % 3;
        if (ks + 2 < nk) { LOADSTAGE((ks + 2) % 3, ks + 2); }
        asm volatile("cp.async.commit_group;" ::: "memory");

        const uint32_t so = sb + (uint32_t)st * 20480u;
#pragma unroll
        for (int kk = 0; kk < 2; kk++) {
            unsigned a0[4], a1[4], b[4][4];
            ldsm4(a0, so + aoff + kk * 32);
            ldsm4(a1, so + aoff + 16 * 80 + kk * 32);
#pragma unroll
            for (int nj = 0; nj < 4; nj++)
                ldsm4(b[nj], so + boff + nj * 16 * 80 + kk * 32);
#pragma unroll
            for (int nj = 0; nj < 4; nj++) {
                mma_f16(acc[0][2 * nj],     a0, &b[nj][0]);
                mma_f16(acc[0][2 * nj + 1], a0, &b[nj][2]);
                mma_f16(acc[1][2 * nj],     a1, &b[nj][0]);
                mma_f16(acc[1][2 * nj + 1], a1, &b[nj][2]);
            }
        }
    }
#undef LOADSTAGE

#pragma unroll
    for (int mi = 0; mi < 2; mi++) {
        const int r0 = bm + moff + 16 * mi + g;
#pragma unroll
        for (int ni = 0; ni < 8; ni++) {
            const int c = bn + noff + 8 * ni + 2 * t;
            float v00 = acc[mi][ni][0], v01 = acc[mi][ni][1];
            float v10 = acc[mi][ni][2], v11 = acc[mi][ni][3];
            if (MODE == 1) {
                const float b0 = bias[c], b1 = bias[c + 1];
                v00 = gelu_exact(v00 + b0); v01 = gelu_exact(v01 + b1);
                v10 = gelu_exact(v10 + b0); v11 = gelu_exact(v11 + b1);
                *(__half2*)(C16 + (size_t)r0 * N + c)       = __floats2half2_rn(v00, v01);
                *(__half2*)(C16 + (size_t)(r0 + 8) * N + c) = __floats2half2_rn(v10, v11);
            } else {
                if (MODE == 2) {
                    if (bias) {
                        const float b0 = bias[c], b1 = bias[c + 1];
                        v00 += b0; v01 += b1; v10 += b0; v11 += b1;
                    }
                    const float2 rr0 = *(const float2*)(resid + (size_t)r0 * N + c);
                    const float2 rr1 = *(const float2*)(resid + (size_t)(r0 + 8) * N + c);
                    v00 += rr0.x; v01 += rr0.y; v10 += rr1.x; v11 += rr1.y;
                }
                float2 o0; o0.x = v00; o0.y = v01;
                float2 o1; o1.x = v10; o1.y = v11;
                *(float2*)(C + (size_t)r0 * N + c) = o0;
                *(float2*)(C + (size_t)(r0 + 8) * N + c) = o1;
            }
        }
    }
}
#define GEMM_SMEM (3 * 20480)

__global__ void conv16(const float* __restrict__ s, __half* __restrict__ d, int n4)
{
    for (int i = blockIdx.x * blockDim.x + threadIdx.x; i < n4; i += gridDim.x * blockDim.x) {
        const float4 v = ((const float4*)s)[i];
        ((__half2*)d)[2 * i]     = __floats2half2_rn(v.x, v.y);
        ((__half2*)d)[2 * i + 1] = __floats2half2_rn(v.z, v.w);
    }
}

__global__ void embed_kernel(const int* __restrict__ ids,
                             const float* __restrict__ emb, float* __restrict__ x)
{
    ((float4*)(x + (size_t)blockIdx.x * DMODEL))[threadIdx.x] =
        ((const float4*)(emb + (size_t)ids[blockIdx.x] * DMODEL))[threadIdx.x];
}

__global__ __launch_bounds__(256)
void layernorm_kernel(const float* __restrict__ x, const float* __restrict__ w,
                      const float* __restrict__ b, __half* __restrict__ y16)
{
    const int row = blockIdx.x, tid = threadIdx.x;
    __shared__ float red[256];

    const float4 v = ((const float4*)(x + (size_t)row * DMODEL))[tid];
    red[tid] = v.x + v.y + v.z + v.w; __syncthreads();
    for (int k = 128; k > 0; k >>= 1) { if (tid < k) red[tid] += red[tid + k]; __syncthreads(); }
    const float mu = red[0] * (1.0f / DMODEL); __syncthreads();

    const float dx = v.x - mu, dy = v.y - mu, dz = v.z - mu, dw = v.w - mu;
    red[tid] = dx * dx + dy * dy + dz * dz + dw * dw; __syncthreads();
    for (int k = 128; k > 0; k >>= 1) { if (tid < k) red[tid] += red[tid + k]; __syncthreads(); }
    const float rs = rsqrtf(red[0] * (1.0f / DMODEL) + 1e-5f);

    const float4 wv = ((const float4*)w)[tid];
    const float4 bv = ((const float4*)b)[tid];
    const __half2 h0 = __floats2half2_rn(dx * rs * wv.x + bv.x, dy * rs * wv.y + bv.y);
    const __half2 h1 = __floats2half2_rn(dz * rs * wv.z + bv.z, dw * rs * wv.w + bv.w);
    uint2 o; o.x = *(const unsigned*)&h0; o.y = *(const unsigned*)&h1;
    ((uint2*)(y16 + (size_t)row * DMODEL))[tid] = o;
}

__global__ __launch_bounds__(256)
void rope_kernel(float* __restrict__ u)
{
    const int idx = blockIdx.x * 256 + threadIdx.x;
    const int row = idx >> 10, j = idx & 1023, s = row & (SEQ - 1);
    const int which = j >> 9, pp = j & 511, head = pp >> 5, i = pp & 31;
    const float inv = exp2f(-(float)(2 * i) * (1.0f / 64.0f) * 13.287712379549449f);
    float sn, cs; sincosf((float)s * inv, &sn, &cs);
    const size_t off = (size_t)row * (3 * TDIM) + (size_t)which * TDIM + head * HDIM + i;
    const float v0 = u[off], v1 = u[off + 32];
    u[off] = v0 * cs - v1 * sn;
    u[off + 32] = v1 * cs + v0 * sn;
}

#define QT 8
__global__ __launch_bounds__(256)
void attn_kernel(const float* __restrict__ u, __half* __restrict__ out16)
{
    const int q0 = blockIdx.x * QT, h = blockIdx.y, b = blockIdx.z;
    const int tid = threadIdx.x, warp = tid >> 5, lane = tid & 31, q = q0 + warp;

    __shared__ float sq[QT][HDIM], ksm[64][65], vsm[64][65];
    const size_t rb = (size_t)(b * SEQ) * (3 * TDIM);

    for (int i = tid; i < QT * HDIM; i += 256)
        sq[i >> 6][i & 63] = u[rb + (size_t)(q0 + (i >> 6)) * (3 * TDIM) + h * HDIM + (i & 63)];
    __syncthreads();

    float qr[HDIM];
#pragma unroll
    for (int j = 0; j < HDIM; j++) qr[j] = sq[warp][j];

    float m = -1e30f, l = 0.0f, a0 = 0.0f, a1 = 0.0f;

    for (int c0 = 0; c0 < q0 + QT; c0 += 64) {
        for (int i4 = tid; i4 < 1024; i4 += 256) {
            const int r = i4 >> 4, c = (i4 & 15) * 4;
            const size_t base = rb + (size_t)(c0 + r) * (3 * TDIM) + h * HDIM + c;
            const float4 kv = *(const float4*)(u + base + TDIM);
            const float4 vv = *(const float4*)(u + base + 2 * TDIM);
            ksm[r][c] = kv.x; ksm[r][c + 1] = kv.y; ksm[r][c + 2] = kv.z; ksm[r][c + 3] = kv.w;
            vsm[r][c] = vv.x; vsm[r][c + 1] = vv.y; vsm[r][c + 2] = vv.z; vsm[r][c + 3] = vv.w;
        }
        __syncthreads();

        float d0 = 0.0f, d1 = 0.0f;
#pragma unroll
        for (int j = 0; j < HDIM; j++) {
            d0 = fmaf(qr[j], ksm[lane][j], d0);
            d1 = fmaf(qr[j], ksm[lane + 32][j], d1);
        }
        d0 *= 0.125f; d1 *= 0.125f;
        const float s0 = (c0 + lane      <= q) ? d0 : -1e30f;
        const float s1 = (c0 + lane + 32 <= q) ? d1 : -1e30f;

        float cm = fmaxf(s0, s1);
#pragma unroll
        for (int o = 16; o > 0; o >>= 1) cm = fmaxf(cm, __shfl_xor_sync(0xffffffff, cm, o));

        const float mn = fmaxf(m, cm), sc = __expf(m - mn);
        const float p0 = __expf(s0 - mn), p1 = __expf(s1 - mn);
        l = l * sc + p0 + p1;
        a0 *= sc; a1 *= sc;

#pragma unroll 8
        for (int r = 0; r < 32; r++) {
            const float pr = __shfl_sync(0xffffffff, p0, r);
            a0 = fmaf(pr, vsm[r][lane], a0);
            a1 = fmaf(pr, vsm[r][lane + 32], a1);
        }
#pragma unroll 8
        for (int r = 0; r < 32; r++) {
            const float pr = __shfl_sync(0xffffffff, p1, r);
            a0 = fmaf(pr, vsm[r + 32][lane], a0);
            a1 = fmaf(pr, vsm[r + 32][lane + 32], a1);
        }
        m = mn;
        __syncthreads();
    }

#pragma unroll
    for (int o = 16; o > 0; o >>= 1) l += __shfl_xor_sync(0xffffffff, l, o);
    const float inv = 1.0f / l;

    const size_t o = (size_t)(b * SEQ + q) * TDIM + h * HDIM + lane;
    out16[o]      = __float2half_rn(a0 * inv);
    out16[o + 32] = __float2half_rn(a1 * inv);
}

extern "C" void kernel_launch(void* const* d_in, const int* in_sizes, int n_in,
                              void* d_out, int out_size)
{
    (void)in_sizes; (void)n_in; (void)out_size;

    const int*   ids = (const int*)  d_in[0];
    const float* emb = (const float*)d_in[1];
    const float* Wu  = (const float*)d_in[2];
    const float* Wo  = (const float*)d_in[3];
    const float* n1w = (const float*)d_in[4];
    const float* n1b = (const float*)d_in[5];
    const float* n2w = (const float*)d_in[6];
    const float* n2b = (const float*)d_in[7];
    const float* f1w = (const float*)d_in[8];
    const float* f1b = (const float*)d_in[9];
    const float* f2w = (const float*)d_in[10];
    const float* f2b = (const float*)d_in[11];
    const float* fnw = (const float*)d_in[12];
    const float* fnb = (const float*)d_in[13];
    float* out = (float*)d_out;

    float *x, *u; __half *xn16, *at16, *h16, *w16;
    cudaGetSymbolAddress((void**)&x,    g_x);
    cudaGetSymbolAddress((void**)&u,    g_u);
    cudaGetSymbolAddress((void**)&xn16, g_xn16);
    cudaGetSymbolAddress((void**)&at16, g_at16);
    cudaGetSymbolAddress((void**)&h16,  g_h16);
    cudaGetSymbolAddress((void**)&w16,  g_w16);

    cudaFuncSetAttribute(gemm_f16<0>, cudaFuncAttributeMaxDynamicSharedMemorySize, GEMM_SMEM);
    cudaFuncSetAttribute(gemm_f16<1>, cudaFuncAttributeMaxDynamicSharedMemorySize, GEMM_SMEM);
    cudaFuncSetAttribute(gemm_f16<2>, cudaFuncAttributeMaxDynamicSharedMemorySize, GEMM_SMEM);

    // one-time per launch: fp32 -> fp16 weight pool
    conv16<<<2048, 256>>>(Wu,  w16 + WU16,  NLAYER * 3 * TDIM * DMODEL / 4);
    conv16<<<2048, 256>>>(Wo,  w16 + WO16,  NLAYER * DMODEL * TDIM / 4);
    conv16<<<2048, 256>>>(f1w, w16 + F116,  NLAYER * FFDIM * DMODEL / 4);
    conv16<<<2048, 256>>>(f2w, w16 + F216,  NLAYER * DMODEL * FFDIM / 4);
    conv16<<<2048, 256>>>(emb, w16 + EMB16, VOCAB * DMODEL / 4);

    embed_kernel<<<NROWS, 256>>>(ids, emb, x);

    for (int l = 0; l < NLAYER; l++) {
        const __half* Wu_l = w16 + WU16 + (size_t)l * 3 * TDIM * DMODEL;
        const __half* Wo_l = w16 + WO16 + (size_t)l * DMODEL * TDIM;
        const __half* f1_l = w16 + F116 + (size_t)l * FFDIM * DMODEL;
        const __half* f2_l = w16 + F216 + (size_t)l * DMODEL * FFDIM;

        layernorm_kernel<<<NROWS, 256>>>(x, n1w + l * DMODEL, n1b + l * DMODEL, xn16);

        gemm_f16<0><<<dim3(3 * TDIM / 128, NROWS / 128), 256, GEMM_SMEM>>>(
            xn16, Wu_l, nullptr, nullptr, u, nullptr, 3 * TDIM, DMODEL);

        rope_kernel<<<(NROWS * 1024) / 256, 256>>>(u);

        attn_kernel<<<dim3(SEQ / QT, NHEAD, BATCH), 256>>>(u, at16);

        gemm_f16<2><<<dim3(DMODEL / 128, NROWS / 128), 256, GEMM_SMEM>>>(
            at16, Wo_l, nullptr, x, x, nullptr, DMODEL, TDIM);

        layernorm_kernel<<<NROWS, 256>>>(x, n2w + l * DMODEL, n2b + l * DMODEL, xn16);

        gemm_f16<1><<<dim3(FFDIM / 128, NROWS / 128), 256, GEMM_SMEM>>>(
            xn16, f1_l, f1b + (size_t)l * FFDIM, nullptr, nullptr, h16, FFDIM, DMODEL);

        gemm_f16<2><<<dim3(DMODEL / 128, NROWS / 128), 256, GEMM_SMEM>>>(
            h16, f2_l, f2b + (size_t)l * DMODEL, x, x, nullptr, DMODEL, FFDIM);
    }

    layernorm_kernel<<<NROWS, 256>>>(x, fnw, fnb, xn16);

    gemm_f16<0><<<dim3(VOCAB / 128, NROWS / 128), 256, GEMM_SMEM>>>(
        xn16, w16 + EMB16, nullptr, nullptr, out, nullptr, VOCAB, DMODEL);
}